// round 16
// baseline (speedup 1.0000x reference)
#include <cuda_runtime.h>
#include <cuda_fp16.h>

#define NN 65536
#define NE 1048576
#define DIN 1024
#define DH 64
#define NC 32

// ---------------- scratch (static device globals; no allocs) ----------------
// Self-cleaning per invocation: g_deg zeroed by in-gemm scan; g_flag/g_sdone/g_tile by k_prep.
__device__ int     g_is64;
__device__ int     g_tile;
__device__ int     g_sdone;
__device__ __align__(16) int   g_deg[NN];
__device__ int     g_bsum[64];
__device__ int     g_flag[64];
__device__ __align__(16) int   g_rowptr[NN + 1];
__device__ __align__(16) int   g_cursor[NN];
__device__ __align__(16) int   g_col[NE];
__device__ __align__(16) float g_dinv[NN];
__device__ __half2 g_y1h[(size_t)NN * 32];   // y1 = dinv*(x@W1), fp16 pairs
__device__ __half  g_y2h[(size_t)NN * NC];   // y2 = dinv*(h@W2), fp16
__device__ __half  g_w1h[DH * DIN];          // W1^T fp16: [n][k]

__device__ __forceinline__ __half2 u2h(unsigned u) { __half2 h; *(unsigned*)&h = u; return h; }

// ---------------- prep: dtype detect + degree count + W transpose + resets ----------------
__global__ void k_prep(const int* __restrict__ w, const float* __restrict__ W1) {
    int i = blockIdx.x * blockDim.x + threadIdx.x;
    int odd = w[2 * i + 1];
    int any = __syncthreads_or(odd);           // any!=0 -> int32 layout
    int d = any ? w[NE + i] : w[2 * (NE + i)];
    atomicAdd(&g_deg[d & (NN - 1)], 1);
    if (i < DIN * DH) {
        int k = i >> 6, n = i & 63;
        g_w1h[n * DIN + k] = __float2half_rn(W1[i]);
    }
    if (i < 64) g_flag[i] = 0;
    if (i == 0) { g_is64 = !any; g_sdone = 0; g_tile = 0; }
}

// ---------------- GEMM1 (HMMA fp16, ldmatrix, double-buffered, occ 3, persistent)
//                  + fused scan (blocks 0-63) + fused CSR fill ----------------
#define SAS 40

__device__ __forceinline__ unsigned smem_u32(const void* p) {
    unsigned a;
    asm("{ .reg .u64 t; cvta.to.shared.u64 t, %1; cvt.u32.u64 %0, t; }" : "=r"(a) : "l"(p));
    return a;
}
__device__ __forceinline__ void ldsm4(unsigned* r, unsigned addr) {
    asm volatile("ldmatrix.sync.aligned.m8n8.x4.shared.b16 {%0,%1,%2,%3}, [%4];"
                 : "=r"(r[0]), "=r"(r[1]), "=r"(r[2]), "=r"(r[3]) : "r"(addr));
}
__device__ __forceinline__ void mma16816(float* d, const unsigned* a, const unsigned* b) {
    asm("mma.sync.aligned.m16n8k16.row.col.f32.f16.f16.f32 "
        "{%0,%1,%2,%3}, {%4,%5,%6,%7}, {%8,%9}, {%0,%1,%2,%3};"
        : "+f"(d[0]), "+f"(d[1]), "+f"(d[2]), "+f"(d[3])
        : "r"(a[0]), "r"(a[1]), "r"(a[2]), "r"(a[3]), "r"(b[0]), "r"(b[1]));
}

#define NTILES (NN / 128)
#define G1GRID 444

__global__ __launch_bounds__(256, 3) void k_gemm1t(const float* __restrict__ A,
                                                   const int* __restrict__ w) {
    __shared__ __half Ah[2][128][SAS], Bh[2][64][SAS];
    __shared__ int s_tile;
    __shared__ int ss[256];
    __shared__ int s_pre;

    int tid = threadIdx.x;
    int b = blockIdx.x;

    // --- fused scan: blocks 0-63, 4 nodes per thread (decoupled lookback) ---
    if (b < 64) {
        int base = b * 1024 + tid * 4;
        int4 d4 = *(int4*)&g_deg[base];
        *(int4*)&g_deg[base] = make_int4(0, 0, 0, 0);   // self-clean for replay
        int s0 = d4.x, s01 = s0 + d4.y, s012 = s01 + d4.z, tot = s012 + d4.w;
        ss[tid] = tot;
        if (tid == 0) s_pre = 0;
        __syncthreads();
        for (int off = 1; off < 256; off <<= 1) {
            int v = (tid >= off) ? ss[tid - off] : 0;
            __syncthreads();
            ss[tid] += v;
            __syncthreads();
        }
        if (tid == 255) {
            g_bsum[b] = ss[255];
            __threadfence();
            atomicExch(&g_flag[b], 1);
        }
        if (tid < b) {
            while (atomicAdd(&g_flag[tid], 0) == 0) { __nanosleep(60); }
            atomicAdd(&s_pre, g_bsum[tid]);
        }
        __syncthreads();
        int excl = ss[tid] - tot + s_pre;
        *(int4*)&g_rowptr[base] = make_int4(excl, excl + s0, excl + s01, excl + s012);
        *(int4*)&g_cursor[base] = make_int4(excl, excl + s0, excl + s01, excl + s012);
        *(float4*)&g_dinv[base] = make_float4(rsqrtf((float)d4.x + 1.0f),
                                              rsqrtf((float)d4.y + 1.0f),
                                              rsqrtf((float)d4.z + 1.0f),
                                              rsqrtf((float)d4.w + 1.0f));
        if (b == 63 && tid == 255) g_rowptr[NN] = NE;
        __syncthreads();
        if (tid == 0) { __threadfence(); atomicAdd(&g_sdone, 1); }
    }

    // --- wait for scan completion (scan blocks first-launched -> resident; no deadlock) ---
    if (tid == 0) {
        while (atomicAdd(&g_sdone, 0) < 64) { __nanosleep(100); }
    }
    __syncthreads();

    // --- fused CSR fill (grid-stride over edges) ---
    {
        int is64 = g_is64;
        for (int i = b * 256 + tid; i < NE; i += G1GRID * 256) {
            int s, d;
            if (is64) { s = w[2 * i]; d = w[2 * (NE + i)]; }
            else      { s = w[i];     d = w[NE + i]; }
            int p = atomicAdd(&g_cursor[d & (NN - 1)], 1);
            g_col[p] = s & (NN - 1);
        }
    }

    int wid = tid >> 5, lane = tid & 31;
    int wm = wid >> 1, wn = wid & 1;
    int g = lane >> 2, t = lane & 3;
    const unsigned* w1h32 = (const unsigned*)g_w1h;

    int a_lrow = (lane & 15);
    int a_lcol = (lane >> 4) * 8;
    unsigned aAddr[2][2], bAddr[2];
#pragma unroll
    for (int bu = 0; bu < 2; bu++) {
#pragma unroll
        for (int mt = 0; mt < 2; mt++) {
            int r0 = wm * 32 + mt * 16;
            aAddr[bu][mt] = smem_u32(&Ah[bu][r0 + a_lrow][a_lcol]);
        }
        bAddr[bu] = smem_u32(&Bh[bu][wn * 32 + lane][0]);
    }

    int srow = tid >> 3, skq = (tid & 7) * 4;
    int sbr  = tid >> 4, sbc = tid & 15;

    for (;;) {
        if (tid == 0) s_tile = atomicAdd(&g_tile, 1);
        __syncthreads();
        int tile = s_tile;
        if (tile >= NTILES) break;
        int blockRow = tile * 128;

        float acc[2][4][4];
#pragma unroll
        for (int mt = 0; mt < 2; mt++)
#pragma unroll
            for (int nt = 0; nt < 4; nt++)
#pragma unroll
                for (int q = 0; q < 4; q++) acc[mt][nt][q] = 0.0f;

        float4 av[4];
        unsigned bhv[4];
#pragma unroll
        for (int i = 0; i < 4; i++) {
            av[i]  = *(const float4*)(A + (size_t)(blockRow + srow + i * 32) * DIN + skq);
            bhv[i] = w1h32[(sbr + i * 16) * (DIN / 2) + sbc];
        }
#pragma unroll
        for (int i = 0; i < 4; i++) {
            __half2 h01 = __float22half2_rn(make_float2(av[i].x, av[i].y));
            __half2 h23 = __float22half2_rn(make_float2(av[i].z, av[i].w));
            *(uint2*)&Ah[0][srow + i * 32][skq] = make_uint2(*(unsigned*)&h01, *(unsigned*)&h23);
            *(unsigned*)&Bh[0][sbr + i * 16][sbc * 2] = bhv[i];
        }
        __syncthreads();

        for (int c = 0; c < 32; c++) {
            int bu = c & 1;
            if (c + 1 < 32) {
                int kt = (c + 1) * 32;
#pragma unroll
                for (int i = 0; i < 4; i++) {
                    av[i]  = *(const float4*)(A + (size_t)(blockRow + srow + i * 32) * DIN + kt + skq);
                    bhv[i] = w1h32[(sbr + i * 16) * (DIN / 2) + kt / 2 + sbc];
                }
            }

#pragma unroll
            for (int kk = 0; kk < 32; kk += 16) {
                unsigned ah[2][4], bb[2][4];
#pragma unroll
                for (int mt = 0; mt < 2; mt++)
                    ldsm4(ah[mt], aAddr[bu][mt] + kk * 2);
                ldsm4(bb[0], bAddr[bu] + kk * 2);
                ldsm4(bb[1], bAddr[bu] + (kk + 8) * 2);
#pragma unroll
                for (int mt = 0; mt < 2; mt++)
#pragma unroll
                    for (int nt = 0; nt < 4; nt++) {
                        unsigned bfr[2] = { bb[0][nt], bb[1][nt] };
                        mma16816(acc[mt][nt], ah[mt], bfr);
                    }
            }

            if (c + 1 < 32) {
#pragma unroll
                for (int i = 0; i < 4; i++) {
                    __half2 h01 = __float22half2_rn(make_float2(av[i].x, av[i].y));
                    __half2 h23 = __float22half2_rn(make_float2(av[i].z, av[i].w));
                    *(uint2*)&Ah[bu ^ 1][srow + i * 32][skq] =
                        make_uint2(*(unsigned*)&h01, *(unsigned*)&h23);
                    *(unsigned*)&Bh[bu ^ 1][sbr + i * 16][sbc * 2] = bhv[i];
                }
            }
            __syncthreads();
        }

#pragma unroll
        for (int mt = 0; mt < 2; mt++) {
            int r0 = blockRow + wm * 32 + mt * 16 + g;
            int r1 = r0 + 8;
            float d0 = g_dinv[r0], d1 = g_dinv[r1];
#pragma unroll
            for (int nt = 0; nt < 4; nt++) {
                int ci = wn * 16 + nt * 4 + t;
                g_y1h[(size_t)r0 * 32 + ci] =
                    __floats2half2_rn(acc[mt][nt][0] * d0, acc[mt][nt][1] * d0);
                g_y1h[(size_t)r1 * 32 + ci] =
                    __floats2half2_rn(acc[mt][nt][2] * d1, acc[mt][nt][3] * d1);
            }
        }
        __syncthreads();
    }
}

// ---------------- layer-1 aggregation + relu + GEMM2 fused (8 lanes per node) ----------------
__global__ __launch_bounds__(256) void k_agg1g2(const float* __restrict__ b1,
                                                const float* __restrict__ W2) {
    __shared__ float4 Ws4[DH][8];   // [k][l8] = {W2[k][l8], W2[k][l8+8], +16, +24}
    for (int i = threadIdx.x; i < DH * 8; i += 256) {
        int k = i >> 3, c = i & 7;
        Ws4[k][c] = make_float4(W2[k * NC + c], W2[k * NC + c + 8],
                                W2[k * NC + c + 16], W2[k * NC + c + 24]);
    }
    __syncthreads();

    int gid = blockIdx.x * 256 + threadIdx.x;
    int node = gid >> 3;
    int l8 = threadIdx.x & 7;
    const uint4* yp4 = (const uint4*)g_y1h;    // row = 8 uint4

    uint4 sv = yp4[(size_t)node * 8 + l8];
    __half2 a0 = u2h(sv.x), a1 = u2h(sv.y), a2 = u2h(sv.z), a3 = u2h(sv.w);

    int e = g_rowptr[node], e1 = g_rowptr[node + 1];
    // peel to 4-alignment for int4 index loads
    for (; e < e1 && (e & 3); e++) {
        uint4 v = yp4[(size_t)g_col[e] * 8 + l8];
        a0 = __hadd2(a0, u2h(v.x));
        a1 = __hadd2(a1, u2h(v.y));
        a2 = __hadd2(a2, u2h(v.z));
        a3 = __hadd2(a3, u2h(v.w));
    }
    for (; e + 4 <= e1; e += 4) {
        int4 ix = *(const int4*)&g_col[e];
        uint4 v0 = yp4[(size_t)ix.x * 8 + l8];
        uint4 v1 = yp4[(size_t)ix.y * 8 + l8];
        uint4 v2 = yp4[(size_t)ix.z * 8 + l8];
        uint4 v3 = yp4[(size_t)ix.w * 8 + l8];
        a0 = __hadd2(a0, __hadd2(__hadd2(u2h(v0.x), u2h(v1.x)), __hadd2(u2h(v2.x), u2h(v3.x))));
        a1 = __hadd2(a1, __hadd2(__hadd2(u2h(v0.y), u2h(v1.y)), __hadd2(u2h(v2.y), u2h(v3.y))));
        a2 = __hadd2(a2, __hadd2(__hadd2(u2h(v0.z), u2h(v1.z)), __hadd2(u2h(v2.z), u2h(v3.z))));
        a3 = __hadd2(a3, __hadd2(__hadd2(u2h(v0.w), u2h(v1.w)), __hadd2(u2h(v2.w), u2h(v3.w))));
    }
    for (; e < e1; e++) {
        uint4 v = yp4[(size_t)g_col[e] * 8 + l8];
        a0 = __hadd2(a0, u2h(v.x));
        a1 = __hadd2(a1, u2h(v.y));
        a2 = __hadd2(a2, u2h(v.z));
        a3 = __hadd2(a3, u2h(v.w));
    }

    float dv = g_dinv[node];
    float4 bb0 = ((const float4*)b1)[l8 * 2];
    float4 bb1 = ((const float4*)b1)[l8 * 2 + 1];
    float2 f0 = __half22float2(a0), f1 = __half22float2(a1);
    float2 f2 = __half22float2(a2), f3 = __half22float2(a3);
    float h[8];
    h[0] = fmaxf(fmaf(dv, f0.x, bb0.x), 0.0f);
    h[1] = fmaxf(fmaf(dv, f0.y, bb0.y), 0.0f);
    h[2] = fmaxf(fmaf(dv, f1.x, bb0.z), 0.0f);
    h[3] = fmaxf(fmaf(dv, f1.y, bb0.w), 0.0f);
    h[4] = fmaxf(fmaf(dv, f2.x, bb1.x), 0.0f);
    h[5] = fmaxf(fmaf(dv, f2.y, bb1.y), 0.0f);
    h[6] = fmaxf(fmaf(dv, f3.x, bb1.z), 0.0f);
    h[7] = fmaxf(fmaf(dv, f3.y, bb1.w), 0.0f);

    float acc0 = 0.0f, acc1 = 0.0f, acc2 = 0.0f, acc3 = 0.0f;
#pragma unroll
    for (int j = 0; j < 8; j++) {
#pragma unroll
        for (int s = 0; s < 8; s++) {
            float hb = __shfl_sync(0xffffffffu, h[j], s, 8);
            float4 wv = Ws4[s * 8 + j][l8];
            acc0 = fmaf(hb, wv.x, acc0);
            acc1 = fmaf(hb, wv.y, acc1);
            acc2 = fmaf(hb, wv.z, acc2);
            acc3 = fmaf(hb, wv.w, acc3);
        }
    }
    __half* y2 = g_y2h + (size_t)node * NC;
    y2[l8]      = __float2half_rn(acc0 * dv);
    y2[l8 + 8]  = __float2half_rn(acc1 * dv);
    y2[l8 + 16] = __float2half_rn(acc2 * dv);
    y2[l8 + 24] = __float2half_rn(acc3 * dv);
}

// ---------------- layer-2 aggregation + log_softmax (8 lanes per node) ----------------
__global__ __launch_bounds__(256) void k_agg2(const float* __restrict__ b2,
                                              float* __restrict__ out) {
    int gid = blockIdx.x * 256 + threadIdx.x;
    int node = gid >> 3;
    int l8 = threadIdx.x & 7;
    const uint2* yp2 = (const uint2*)g_y2h;    // row = 8 uint2

    uint2 sv = yp2[(size_t)node * 8 + l8];
    __half2 a0 = u2h(sv.x), a1 = u2h(sv.y);

    int e = g_rowptr[node], e1 = g_rowptr[node + 1];
    for (; e < e1 && (e & 3); e++) {
        uint2 v = yp2[(size_t)g_col[e] * 8 + l8];
        a0 = __hadd2(a0, u2h(v.x));
        a1 = __hadd2(a1, u2h(v.y));
    }
    for (; e + 4 <= e1; e += 4) {
        int4 ix = *(const int4*)&g_col[e];
        uint2 v0 = yp2[(size_t)ix.x * 8 + l8];
        uint2 v1 = yp2[(size_t)ix.y * 8 + l8];
        uint2 v2 = yp2[(size_t)ix.z * 8 + l8];
        uint2 v3 = yp2[(size_t)ix.w * 8 + l8];
        a0 = __hadd2(a0, __hadd2(__hadd2(u2h(v0.x), u2h(v1.x)), __hadd2(u2h(v2.x), u2h(v3.x))));
        a1 = __hadd2(a1, __hadd2(__hadd2(u2h(v0.y), u2h(v1.y)), __hadd2(u2h(v2.y), u2h(v3.y))));
    }
    for (; e < e1; e++) {
        uint2 v = yp2[(size_t)g_col[e] * 8 + l8];
        a0 = __hadd2(a0, u2h(v.x));
        a1 = __hadd2(a1, u2h(v.y));
    }

    float dv = g_dinv[node];
    float4 bb = ((const float4*)b2)[l8];
    float2 f0 = __half22float2(a0), f1 = __half22float2(a1);
    float v0 = fmaf(dv, f0.x, bb.x);
    float v1 = fmaf(dv, f0.y, bb.y);
    float v2 = fmaf(dv, f1.x, bb.z);
    float v3 = fmaf(dv, f1.y, bb.w);

    float mx = fmaxf(fmaxf(v0, v1), fmaxf(v2, v3));
#pragma unroll
    for (int o = 4; o; o >>= 1) mx = fmaxf(mx, __shfl_xor_sync(0xffffffffu, mx, o));
    float sm = __expf(v0 - mx) + __expf(v1 - mx) + __expf(v2 - mx) + __expf(v3 - mx);
#pragma unroll
    for (int o = 4; o; o >>= 1) sm += __shfl_xor_sync(0xffffffffu, sm, o);
    float lse = mx + logf(sm);
    ((float4*)out)[(size_t)node * 8 + l8] = make_float4(v0 - lse, v1 - lse, v2 - lse, v3 - lse);
}

// ---------------- launch (4 kernels) ----------------
extern "C" void kernel_launch(void* const* d_in, const int* in_sizes, int n_in,
                              void* d_out, int out_size) {
    const float* x  = (const float*)d_in[0];
    const int*   ei = (const int*)d_in[1];
    const float* W1 = (const float*)d_in[2];
    const float* b1 = (const float*)d_in[3];
    const float* W2 = (const float*)d_in[4];
    const float* b2 = (const float*)d_in[5];
    float* out = (float*)d_out;

    k_prep  <<<NE / 256, 256>>>(ei, W1);
    k_gemm1t<<<G1GRID, 256>>>(x, ei);
    k_agg1g2<<<NN * 8 / 256, 256>>>(b1, W2);
    k_agg2  <<<NN * 8 / 256, 256>>>(b2, out);
}

// round 17
// speedup vs baseline: 1.0029x; 1.0029x over previous
#include <cuda_runtime.h>
#include <cuda_fp16.h>

#define NN 65536
#define NE 1048576
#define DIN 1024
#define DH 64
#define NC 32

// ---------------- scratch (static device globals; no allocs) ----------------
// Self-cleaning per invocation: g_deg zeroed by in-gemm scan; g_flag/g_sdone/g_tile by k_prep.
__device__ int     g_is64;
__device__ int     g_tile;
__device__ int     g_sdone;
__device__ __align__(16) int   g_deg[NN];
__device__ int     g_bsum[64];
__device__ int     g_flag[64];
__device__ __align__(16) int   g_rowptr[NN + 1];
__device__ __align__(16) int   g_cursor[NN];
__device__ __align__(16) int   g_col[NE];
__device__ __align__(16) float g_dinv[NN];
__device__ __half2 g_y1h[(size_t)NN * 32];   // y1 = dinv*(x@W1), fp16 pairs
__device__ __half  g_y2h[(size_t)NN * NC];   // y2 = dinv*(h@W2), fp16
__device__ __half  g_w1h[DH * DIN];          // W1^T fp16: [n][k]

__device__ __forceinline__ __half2 u2h(unsigned u) { __half2 h; *(unsigned*)&h = u; return h; }

// ---------------- prep: dtype detect + degree count + W transpose + resets ----------------
__global__ void k_prep(const int* __restrict__ w, const float* __restrict__ W1) {
    int i = blockIdx.x * blockDim.x + threadIdx.x;
    int odd = w[2 * i + 1];
    int any = __syncthreads_or(odd);           // any!=0 -> int32 layout
    int d = any ? w[NE + i] : w[2 * (NE + i)];
    atomicAdd(&g_deg[d & (NN - 1)], 1);
    if (i < DIN * DH) {
        int k = i >> 6, n = i & 63;
        g_w1h[n * DIN + k] = __float2half_rn(W1[i]);
    }
    if (i < 64) g_flag[i] = 0;
    if (i == 0) { g_is64 = !any; g_sdone = 0; g_tile = 0; }
}

// ---------------- GEMM1 (HMMA fp16, ldmatrix, double-buffered, occ 3, persistent)
//                  + fused scan (blocks 0-63) + fused CSR fill ----------------
#define SAS 40

__device__ __forceinline__ unsigned smem_u32(const void* p) {
    unsigned a;
    asm("{ .reg .u64 t; cvta.to.shared.u64 t, %1; cvt.u32.u64 %0, t; }" : "=r"(a) : "l"(p));
    return a;
}
__device__ __forceinline__ void ldsm4(unsigned* r, unsigned addr) {
    asm volatile("ldmatrix.sync.aligned.m8n8.x4.shared.b16 {%0,%1,%2,%3}, [%4];"
                 : "=r"(r[0]), "=r"(r[1]), "=r"(r[2]), "=r"(r[3]) : "r"(addr));
}
__device__ __forceinline__ void mma16816(float* d, const unsigned* a, const unsigned* b) {
    asm("mma.sync.aligned.m16n8k16.row.col.f32.f16.f16.f32 "
        "{%0,%1,%2,%3}, {%4,%5,%6,%7}, {%8,%9}, {%0,%1,%2,%3};"
        : "+f"(d[0]), "+f"(d[1]), "+f"(d[2]), "+f"(d[3])
        : "r"(a[0]), "r"(a[1]), "r"(a[2]), "r"(a[3]), "r"(b[0]), "r"(b[1]));
}

#define NTILES (NN / 128)
#define G1GRID 444

__global__ __launch_bounds__(256, 3) void k_gemm1t(const float* __restrict__ A,
                                                   const int* __restrict__ w) {
    __shared__ __half Ah[2][128][SAS], Bh[2][64][SAS];
    __shared__ int s_tile;
    __shared__ int ss[256];
    __shared__ int s_pre;

    int tid = threadIdx.x;
    int b = blockIdx.x;

    // --- fused scan: blocks 0-63, 4 nodes per thread (decoupled lookback) ---
    if (b < 64) {
        int base = b * 1024 + tid * 4;
        int4 d4 = *(int4*)&g_deg[base];
        *(int4*)&g_deg[base] = make_int4(0, 0, 0, 0);   // self-clean for replay
        int s0 = d4.x, s01 = s0 + d4.y, s012 = s01 + d4.z, tot = s012 + d4.w;
        ss[tid] = tot;
        if (tid == 0) s_pre = 0;
        __syncthreads();
        for (int off = 1; off < 256; off <<= 1) {
            int v = (tid >= off) ? ss[tid - off] : 0;
            __syncthreads();
            ss[tid] += v;
            __syncthreads();
        }
        if (tid == 255) {
            g_bsum[b] = ss[255];
            __threadfence();
            atomicExch(&g_flag[b], 1);
        }
        if (tid < b) {
            while (atomicAdd(&g_flag[tid], 0) == 0) { __nanosleep(60); }
            atomicAdd(&s_pre, g_bsum[tid]);
        }
        __syncthreads();
        int excl = ss[tid] - tot + s_pre;
        *(int4*)&g_rowptr[base] = make_int4(excl, excl + s0, excl + s01, excl + s012);
        *(int4*)&g_cursor[base] = make_int4(excl, excl + s0, excl + s01, excl + s012);
        *(float4*)&g_dinv[base] = make_float4(rsqrtf((float)d4.x + 1.0f),
                                              rsqrtf((float)d4.y + 1.0f),
                                              rsqrtf((float)d4.z + 1.0f),
                                              rsqrtf((float)d4.w + 1.0f));
        if (b == 63 && tid == 255) g_rowptr[NN] = NE;
        __syncthreads();
        if (tid == 0) { __threadfence(); atomicAdd(&g_sdone, 1); }
    }

    // --- wait for scan completion (scan blocks first-launched -> resident; no deadlock) ---
    if (tid == 0) {
        while (atomicAdd(&g_sdone, 0) < 64) { __nanosleep(100); }
    }
    __syncthreads();

    // --- fused CSR fill (grid-stride over edges) ---
    {
        int is64 = g_is64;
        for (int i = b * 256 + tid; i < NE; i += G1GRID * 256) {
            int s, d;
            if (is64) { s = w[2 * i]; d = w[2 * (NE + i)]; }
            else      { s = w[i];     d = w[NE + i]; }
            int p = atomicAdd(&g_cursor[d & (NN - 1)], 1);
            g_col[p] = s & (NN - 1);
        }
    }

    int wid = tid >> 5, lane = tid & 31;
    int wm = wid >> 1, wn = wid & 1;
    int g = lane >> 2, t = lane & 3;
    const unsigned* w1h32 = (const unsigned*)g_w1h;

    int a_lrow = (lane & 15);
    int a_lcol = (lane >> 4) * 8;
    unsigned aAddr[2][2], bAddr[2];
#pragma unroll
    for (int bu = 0; bu < 2; bu++) {
#pragma unroll
        for (int mt = 0; mt < 2; mt++) {
            int r0 = wm * 32 + mt * 16;
            aAddr[bu][mt] = smem_u32(&Ah[bu][r0 + a_lrow][a_lcol]);
        }
        bAddr[bu] = smem_u32(&Bh[bu][wn * 32 + lane][0]);
    }

    int srow = tid >> 3, skq = (tid & 7) * 4;
    int sbr  = tid >> 4, sbc = tid & 15;

    for (;;) {
        if (tid == 0) s_tile = atomicAdd(&g_tile, 1);
        __syncthreads();
        int tile = s_tile;
        if (tile >= NTILES) break;
        int blockRow = tile * 128;

        float acc[2][4][4];
#pragma unroll
        for (int mt = 0; mt < 2; mt++)
#pragma unroll
            for (int nt = 0; nt < 4; nt++)
#pragma unroll
                for (int q = 0; q < 4; q++) acc[mt][nt][q] = 0.0f;

        float4 av[4];
        unsigned bhv[4];
#pragma unroll
        for (int i = 0; i < 4; i++) {
            av[i]  = *(const float4*)(A + (size_t)(blockRow + srow + i * 32) * DIN + skq);
            bhv[i] = w1h32[(sbr + i * 16) * (DIN / 2) + sbc];
        }
#pragma unroll
        for (int i = 0; i < 4; i++) {
            __half2 h01 = __float22half2_rn(make_float2(av[i].x, av[i].y));
            __half2 h23 = __float22half2_rn(make_float2(av[i].z, av[i].w));
            *(uint2*)&Ah[0][srow + i * 32][skq] = make_uint2(*(unsigned*)&h01, *(unsigned*)&h23);
            *(unsigned*)&Bh[0][sbr + i * 16][sbc * 2] = bhv[i];
        }
        __syncthreads();

        for (int c = 0; c < 32; c++) {
            int bu = c & 1;
            if (c + 1 < 32) {
                int kt = (c + 1) * 32;
#pragma unroll
                for (int i = 0; i < 4; i++) {
                    av[i]  = *(const float4*)(A + (size_t)(blockRow + srow + i * 32) * DIN + kt + skq);
                    bhv[i] = w1h32[(sbr + i * 16) * (DIN / 2) + kt / 2 + sbc];
                }
            }

#pragma unroll
            for (int kk = 0; kk < 32; kk += 16) {
                unsigned ah[2][4], bb[2][4];
#pragma unroll
                for (int mt = 0; mt < 2; mt++)
                    ldsm4(ah[mt], aAddr[bu][mt] + kk * 2);
                ldsm4(bb[0], bAddr[bu] + kk * 2);
                ldsm4(bb[1], bAddr[bu] + (kk + 8) * 2);
#pragma unroll
                for (int mt = 0; mt < 2; mt++)
#pragma unroll
                    for (int nt = 0; nt < 4; nt++) {
                        unsigned bfr[2] = { bb[0][nt], bb[1][nt] };
                        mma16816(acc[mt][nt], ah[mt], bfr);
                    }
            }

            if (c + 1 < 32) {
#pragma unroll
                for (int i = 0; i < 4; i++) {
                    __half2 h01 = __float22half2_rn(make_float2(av[i].x, av[i].y));
                    __half2 h23 = __float22half2_rn(make_float2(av[i].z, av[i].w));
                    *(uint2*)&Ah[bu ^ 1][srow + i * 32][skq] =
                        make_uint2(*(unsigned*)&h01, *(unsigned*)&h23);
                    *(unsigned*)&Bh[bu ^ 1][sbr + i * 16][sbc * 2] = bhv[i];
                }
            }
            __syncthreads();
        }

#pragma unroll
        for (int mt = 0; mt < 2; mt++) {
            int r0 = blockRow + wm * 32 + mt * 16 + g;
            int r1 = r0 + 8;
            float d0 = g_dinv[r0], d1 = g_dinv[r1];
#pragma unroll
            for (int nt = 0; nt < 4; nt++) {
                int ci = wn * 16 + nt * 4 + t;
                g_y1h[(size_t)r0 * 32 + ci] =
                    __floats2half2_rn(acc[mt][nt][0] * d0, acc[mt][nt][1] * d0);
                g_y1h[(size_t)r1 * 32 + ci] =
                    __floats2half2_rn(acc[mt][nt][2] * d1, acc[mt][nt][3] * d1);
            }
        }
        __syncthreads();
    }
}

// ---------------- layer-1 aggregation + relu + GEMM2 fused (8 lanes per node, MLP 8) ----------------
__global__ __launch_bounds__(256) void k_agg1g2(const float* __restrict__ b1,
                                                const float* __restrict__ W2) {
    __shared__ float4 Ws4[DH][8];   // [k][l8] = {W2[k][l8], W2[k][l8+8], +16, +24}
    for (int i = threadIdx.x; i < DH * 8; i += 256) {
        int k = i >> 3, c = i & 7;
        Ws4[k][c] = make_float4(W2[k * NC + c], W2[k * NC + c + 8],
                                W2[k * NC + c + 16], W2[k * NC + c + 24]);
    }
    __syncthreads();

    int gid = blockIdx.x * 256 + threadIdx.x;
    int node = gid >> 3;
    int l8 = threadIdx.x & 7;
    const uint4* yp4 = (const uint4*)g_y1h;    // row = 8 uint4

    uint4 sv = yp4[(size_t)node * 8 + l8];
    __half2 a0 = u2h(sv.x), a1 = u2h(sv.y), a2 = u2h(sv.z), a3 = u2h(sv.w);

    int e = g_rowptr[node], e1 = g_rowptr[node + 1];
    for (; e + 8 <= e1; e += 8) {
        uint4 v0 = yp4[(size_t)g_col[e]     * 8 + l8];
        uint4 v1 = yp4[(size_t)g_col[e + 1] * 8 + l8];
        uint4 v2 = yp4[(size_t)g_col[e + 2] * 8 + l8];
        uint4 v3 = yp4[(size_t)g_col[e + 3] * 8 + l8];
        uint4 v4 = yp4[(size_t)g_col[e + 4] * 8 + l8];
        uint4 v5 = yp4[(size_t)g_col[e + 5] * 8 + l8];
        uint4 v6 = yp4[(size_t)g_col[e + 6] * 8 + l8];
        uint4 v7 = yp4[(size_t)g_col[e + 7] * 8 + l8];
        a0 = __hadd2(a0, __hadd2(__hadd2(__hadd2(u2h(v0.x), u2h(v1.x)), __hadd2(u2h(v2.x), u2h(v3.x))),
                                 __hadd2(__hadd2(u2h(v4.x), u2h(v5.x)), __hadd2(u2h(v6.x), u2h(v7.x)))));
        a1 = __hadd2(a1, __hadd2(__hadd2(__hadd2(u2h(v0.y), u2h(v1.y)), __hadd2(u2h(v2.y), u2h(v3.y))),
                                 __hadd2(__hadd2(u2h(v4.y), u2h(v5.y)), __hadd2(u2h(v6.y), u2h(v7.y)))));
        a2 = __hadd2(a2, __hadd2(__hadd2(__hadd2(u2h(v0.z), u2h(v1.z)), __hadd2(u2h(v2.z), u2h(v3.z))),
                                 __hadd2(__hadd2(u2h(v4.z), u2h(v5.z)), __hadd2(u2h(v6.z), u2h(v7.z)))));
        a3 = __hadd2(a3, __hadd2(__hadd2(__hadd2(u2h(v0.w), u2h(v1.w)), __hadd2(u2h(v2.w), u2h(v3.w))),
                                 __hadd2(__hadd2(u2h(v4.w), u2h(v5.w)), __hadd2(u2h(v6.w), u2h(v7.w)))));
    }
    for (; e + 4 <= e1; e += 4) {
        uint4 v0 = yp4[(size_t)g_col[e]     * 8 + l8];
        uint4 v1 = yp4[(size_t)g_col[e + 1] * 8 + l8];
        uint4 v2 = yp4[(size_t)g_col[e + 2] * 8 + l8];
        uint4 v3 = yp4[(size_t)g_col[e + 3] * 8 + l8];
        a0 = __hadd2(a0, __hadd2(__hadd2(u2h(v0.x), u2h(v1.x)), __hadd2(u2h(v2.x), u2h(v3.x))));
        a1 = __hadd2(a1, __hadd2(__hadd2(u2h(v0.y), u2h(v1.y)), __hadd2(u2h(v2.y), u2h(v3.y))));
        a2 = __hadd2(a2, __hadd2(__hadd2(u2h(v0.z), u2h(v1.z)), __hadd2(u2h(v2.z), u2h(v3.z))));
        a3 = __hadd2(a3, __hadd2(__hadd2(u2h(v0.w), u2h(v1.w)), __hadd2(u2h(v2.w), u2h(v3.w))));
    }
    for (; e < e1; e++) {
        uint4 v = yp4[(size_t)g_col[e] * 8 + l8];
        a0 = __hadd2(a0, u2h(v.x));
        a1 = __hadd2(a1, u2h(v.y));
        a2 = __hadd2(a2, u2h(v.z));
        a3 = __hadd2(a3, u2h(v.w));
    }

    float dv = g_dinv[node];
    float4 bb0 = ((const float4*)b1)[l8 * 2];
    float4 bb1 = ((const float4*)b1)[l8 * 2 + 1];
    float2 f0 = __half22float2(a0), f1 = __half22float2(a1);
    float2 f2 = __half22float2(a2), f3 = __half22float2(a3);
    float h[8];
    h[0] = fmaxf(fmaf(dv, f0.x, bb0.x), 0.0f);
    h[1] = fmaxf(fmaf(dv, f0.y, bb0.y), 0.0f);
    h[2] = fmaxf(fmaf(dv, f1.x, bb0.z), 0.0f);
    h[3] = fmaxf(fmaf(dv, f1.y, bb0.w), 0.0f);
    h[4] = fmaxf(fmaf(dv, f2.x, bb1.x), 0.0f);
    h[5] = fmaxf(fmaf(dv, f2.y, bb1.y), 0.0f);
    h[6] = fmaxf(fmaf(dv, f3.x, bb1.z), 0.0f);
    h[7] = fmaxf(fmaf(dv, f3.y, bb1.w), 0.0f);

    float acc0 = 0.0f, acc1 = 0.0f, acc2 = 0.0f, acc3 = 0.0f;
#pragma unroll
    for (int j = 0; j < 8; j++) {
#pragma unroll
        for (int s = 0; s < 8; s++) {
            float hb = __shfl_sync(0xffffffffu, h[j], s, 8);
            float4 wv = Ws4[s * 8 + j][l8];
            acc0 = fmaf(hb, wv.x, acc0);
            acc1 = fmaf(hb, wv.y, acc1);
            acc2 = fmaf(hb, wv.z, acc2);
            acc3 = fmaf(hb, wv.w, acc3);
        }
    }
    __half* y2 = g_y2h + (size_t)node * NC;
    y2[l8]      = __float2half_rn(acc0 * dv);
    y2[l8 + 8]  = __float2half_rn(acc1 * dv);
    y2[l8 + 16] = __float2half_rn(acc2 * dv);
    y2[l8 + 24] = __float2half_rn(acc3 * dv);
}

// ---------------- layer-2 aggregation + log_softmax (8 lanes per node) ----------------
__global__ __launch_bounds__(256) void k_agg2(const float* __restrict__ b2,
                                              float* __restrict__ out) {
    int gid = blockIdx.x * 256 + threadIdx.x;
    int node = gid >> 3;
    int l8 = threadIdx.x & 7;
    const uint2* yp2 = (const uint2*)g_y2h;    // row = 8 uint2

    uint2 sv = yp2[(size_t)node * 8 + l8];
    __half2 a0 = u2h(sv.x), a1 = u2h(sv.y);

    int e = g_rowptr[node], e1 = g_rowptr[node + 1];
    for (; e + 4 <= e1; e += 4) {
        uint2 v0 = yp2[(size_t)g_col[e]     * 8 + l8];
        uint2 v1 = yp2[(size_t)g_col[e + 1] * 8 + l8];
        uint2 v2 = yp2[(size_t)g_col[e + 2] * 8 + l8];
        uint2 v3 = yp2[(size_t)g_col[e + 3] * 8 + l8];
        a0 = __hadd2(a0, __hadd2(__hadd2(u2h(v0.x), u2h(v1.x)), __hadd2(u2h(v2.x), u2h(v3.x))));
        a1 = __hadd2(a1, __hadd2(__hadd2(u2h(v0.y), u2h(v1.y)), __hadd2(u2h(v2.y), u2h(v3.y))));
    }
    for (; e < e1; e++) {
        uint2 v = yp2[(size_t)g_col[e] * 8 + l8];
        a0 = __hadd2(a0, u2h(v.x));
        a1 = __hadd2(a1, u2h(v.y));
    }

    float dv = g_dinv[node];
    float4 bb = ((const float4*)b2)[l8];
    float2 f0 = __half22float2(a0), f1 = __half22float2(a1);
    float v0 = fmaf(dv, f0.x, bb.x);
    float v1 = fmaf(dv, f0.y, bb.y);
    float v2 = fmaf(dv, f1.x, bb.z);
    float v3 = fmaf(dv, f1.y, bb.w);

    float mx = fmaxf(fmaxf(v0, v1), fmaxf(v2, v3));
#pragma unroll
    for (int o = 4; o; o >>= 1) mx = fmaxf(mx, __shfl_xor_sync(0xffffffffu, mx, o));
    float sm = __expf(v0 - mx) + __expf(v1 - mx) + __expf(v2 - mx) + __expf(v3 - mx);
#pragma unroll
    for (int o = 4; o; o >>= 1) sm += __shfl_xor_sync(0xffffffffu, sm, o);
    float lse = mx + logf(sm);
    ((float4*)out)[(size_t)node * 8 + l8] = make_float4(v0 - lse, v1 - lse, v2 - lse, v3 - lse);
}

// ---------------- launch (4 kernels) ----------------
extern "C" void kernel_launch(void* const* d_in, const int* in_sizes, int n_in,
                              void* d_out, int out_size) {
    const float* x  = (const float*)d_in[0];
    const int*   ei = (const int*)d_in[1];
    const float* W1 = (const float*)d_in[2];
    const float* b1 = (const float*)d_in[3];
    const float* W2 = (const float*)d_in[4];
    const float* b2 = (const float*)d_in[5];
    float* out = (float*)d_out;

    k_prep  <<<NE / 256, 256>>>(ei, W1);
    k_gemm1t<<<G1GRID, 256>>>(x, ei);
    k_agg1g2<<<NN * 8 / 256, 256>>>(b1, W2);
    k_agg2  <<<NN * 8 / 256, 256>>>(b2, out);
}